// round 12
// baseline (speedup 1.0000x reference)
#include <cuda_runtime.h>
#include <cuda_bf16.h>
#include <mma.h>

// Problem sizes (fixed by the dataset)
#define NN 65536
#define DD 32
#define HH 1024
#define CC 64

// Triangular staged-weight layout (see k_main):
//   sw2 region: sum_d L(d)      = 16399 float2  (L(d)=33d+1, L(0)=0)
//   sw1 region: sum_d (1024-L)  = 16369 float
#define SW2_F2   16399
#define SW1_F    16369
#define SW2_BYTES (SW2_F2 * 8)
#define SMEM_MAIN_BYTES (SW2_BYTES + SW1_F * 4)   // 196,668 B < 228 KB

// Degree-sorted unit layout:
//   deg(h) = h % 31 + 1; sorted prefix cum(g) = 33g+1 holds exactly units deg<=g
//   (deg 1 has 34 units, deg 2..31 have 33 each; cum(31)=1024).
// perm(j) = original unit index of sorted slot j.
__device__ __forceinline__ int perm_unit(int j) {
    int g, k;
    if (j < 34) { g = 1; k = j; }
    else        { g = (j - 1) / 33 + 1; k = j - (33 * (g - 1) + 1); }
    return (g - 1) + 31 * k;
}

// Fast, accurate-enough tanh: 1 - 2/(1+e^{2x}).
// ex2.approx rel err ~2^-22, rcp.approx ~2^-23 -> abs err ~1e-6; saturates
// correctly at +/-inf.
__device__ __forceinline__ float tanh_fast(float v) {
    float e, r;
    asm("ex2.approx.f32 %0, %1;" : "=f"(e) : "f"(v * 2.885390081777927f)); // 2*log2(e)
    asm("rcp.approx.f32 %0, %1;" : "=f"(r) : "f"(e + 1.0f));
    return fmaf(-2.0f, r, 1.0f);
}

// Scratch (device globals: allocation-free per harness rules)
__device__ float  g_pre[(size_t)NN * HH];   // 256 MB: context@Wc + b1 (permuted cols)
__device__ float  g_W1p[DD * HH];           // W1p[d][j] = W1[d][perm(j)]
__device__ float2 g_W2p[DD * HH];           // W2p[d][j] = W2[perm(j)][d][0..1]
__device__ float  g_Wcp[CC * HH];           // Wcp[c][j] = Wc[c][perm(j)]
__device__ float  g_b1p[HH];

// ---------------------------------------------------------------------------
// Kernel 1: permute weights into degree-sorted order
// ---------------------------------------------------------------------------
__global__ void k_permute(const float* __restrict__ W1, const float* __restrict__ b1,
                          const float* __restrict__ Wc, const float* __restrict__ W2) {
    int j = blockIdx.x * blockDim.x + threadIdx.x;
    if (j >= HH) return;
    int h = perm_unit(j);
    g_b1p[j] = b1[h];
#pragma unroll
    for (int d = 0; d < DD; d++) g_W1p[d * HH + j] = W1[d * HH + h];
#pragma unroll
    for (int c = 0; c < CC; c++) g_Wcp[c * HH + j] = Wc[c * HH + h];
#pragma unroll
    for (int d = 0; d < DD; d++)
        g_W2p[d * HH + j] = make_float2(W2[h * (DD * 2) + d * 2 + 0],
                                        W2[h * (DD * 2) + d * 2 + 1]);
}

// ---------------------------------------------------------------------------
// Kernel 2: pre[n][j] = sum_c context[n][c] * Wcp[c][j] + b1p[j]
// tf32x3 wmma (m16n16k8), fp32 accumulate. B-SHARING layout: all 4 warps of a
// block use the SAME 64-col B tile (ct from blockIdx) and 4 different 16-row
// A tiles -> B comes from L1 after warp 0, cutting L2 B traffic 4x.
// ---------------------------------------------------------------------------
__global__ __launch_bounds__(128)
void k_pregemm(const float* __restrict__ ctx) {
    using namespace nvcuda;
    __shared__ float tile[4][16 * 64];

    int warpId = threadIdx.x >> 5;
    int lane   = threadIdx.x & 31;
    int ct = blockIdx.x & 15;                     // col group: 64 cols (shared by block)
    int rt = (blockIdx.x >> 4) * 4 + warpId;      // row tile: 16 rows (per warp)

    const float* Aptr = ctx + (size_t)rt * 16 * CC;

    wmma::fragment<wmma::accumulator, 16, 16, 8, float> acc[4];
#pragma unroll
    for (int c = 0; c < 4; c++) wmma::fill_fragment(acc[c], 0.0f);

#pragma unroll
    for (int k = 0; k < CC; k += 8) {
        wmma::fragment<wmma::matrix_a, 16, 16, 8, wmma::precision::tf32, wmma::row_major> aHi, aLo;
        wmma::load_matrix_sync(aHi, Aptr + k, CC);
#pragma unroll
        for (int t = 0; t < aHi.num_elements; t++) {
            float f  = aHi.x[t];
            float hi = wmma::__float_to_tf32(f);
            aHi.x[t] = hi;
            aLo.x[t] = wmma::__float_to_tf32(f - hi);
        }
#pragma unroll
        for (int c = 0; c < 4; c++) {
            wmma::fragment<wmma::matrix_b, 16, 16, 8, wmma::precision::tf32, wmma::row_major> bHi, bLo;
            wmma::load_matrix_sync(bHi, g_Wcp + k * HH + ct * 64 + c * 16, HH);
#pragma unroll
            for (int t = 0; t < bHi.num_elements; t++) {
                float f  = bHi.x[t];
                float hi = wmma::__float_to_tf32(f);
                bHi.x[t] = hi;
                bLo.x[t] = wmma::__float_to_tf32(f - hi);
            }
            wmma::mma_sync(acc[c], aHi, bHi, acc[c]);
            wmma::mma_sync(acc[c], aLo, bHi, acc[c]);
            wmma::mma_sync(acc[c], aHi, bLo, acc[c]);
        }
    }

    float* tw = &tile[warpId][0];
#pragma unroll
    for (int c = 0; c < 4; c++)
        wmma::store_matrix_sync(tw + c * 16, acc[c], 64, wmma::mem_row_major);
    __syncwarp();

    for (int i = lane; i < 16 * 64; i += 32) {
        int r = i >> 6, cc = i & 63;
        int col = ct * 64 + cc;
        g_pre[(size_t)(rt * 16 + r) * HH + col] = tw[r * 64 + cc] + g_b1p[col];
    }
}

// ---------------------------------------------------------------------------
// Kernel 3: sequential MADE sampling. One warp owns FOUR rows; state z[1024]
// per row in registers. 4 UNROLLED groups x 8 ROLLED d-steps (static r-bounds
// per group -> register residency + small code).
// BRANCH-FREE inner loops: weight LDS unconditional (proven in-bounds in the
// packed triangular layout), accumulate/update are predicated selects -> no
// BSSY/BSYNC storm. tanh stays branch-guarded but only on the 9 statically
// identified candidate slices per group (band union = [8g-1, 8g+7]).
// ---------------------------------------------------------------------------
__global__ __launch_bounds__(256, 1)
void k_main(const float* __restrict__ x, const float* __restrict__ b2,
            float* __restrict__ out) {
    extern __shared__ char dynsmem[];
    float2* sm2 = (float2*)dynsmem;               // packed W2 prefixes
    float*  sm1 = (float*)(dynsmem + SW2_BYTES);  // packed W1 suffixes

    const int tid = threadIdx.x;
    const int lane = tid & 31;
    const int warpId = tid >> 5;

    // -------- stage the full triangular weight set (once, rolled/compact) ----
    {
        int o1 = 0, o2 = 0;
        for (int d = 0; d < DD; d++) {
            const int L = d ? 33 * d + 1 : 0;
            for (int i = tid; i < L; i += 256)      sm2[o2 + i] = g_W2p[d * HH + i];
            for (int i = tid; i < HH - L; i += 256) sm1[o1 + i] = g_W1p[d * HH + L + i];
            o2 += L; o1 += HH - L;
        }
    }

    // -------- per-warp row state --------
    const int nb = blockIdx.x * 32 + warpId * 4;   // 4 consecutive rows per warp
    float s[4][32];
    float xv[4], yacc[4], ld[4];
#pragma unroll
    for (int j = 0; j < 4; j++) {
        const float* p = g_pre + (size_t)(nb + j) * HH;
#pragma unroll
        for (int r = 0; r < 32; r++) s[j][r] = p[r * 32 + lane];
        xv[j] = x[(nb + j) * DD + lane];
        yacc[j] = 0.f; ld[j] = 0.f;
    }
    // b2 held lane-wise: lane d owns (shift_bias, logscale_bias) of dim d
    float b2s = b2[2 * lane + 0];
    float b2l = b2[2 * lane + 1];

    __syncthreads();   // staged weights visible; only barrier in the kernel

    int o1 = 0, o2 = 0;
#pragma unroll
    for (int grp = 0; grp < 4; grp++) {
        const int R_RD  = 8 * (grp + 1);             // static: read slices [0, R_RD)
        const int R_UP  = 8 * grp;                   // static: update slices [R_UP, 32)
        const int FR_LO = (grp > 0) ? 8 * grp - 1 : 0;  // static tanh candidates
        const int FR_HI = 8 * grp + 7;

#pragma unroll 1
        for (int dd = 0; dd < 8; dd++) {
            const int d   = grp * 8 + dd;
            const int L   = d ? 33 * d + 1 : 0;              // read set [0, L)
            const int fLo = (d >= 2) ? 33 * (d - 1) + 1 : 0; // freeze [fLo, L)
            const float2* w2s = sm2 + o2;                    // valid u in [0, L)
            const float*  w1s = sm1 + (o1 - L);              // valid u in [L, 1024)

            float as[4] = {0.f, 0.f, 0.f, 0.f};
            float al[4] = {0.f, 0.f, 0.f, 0.f};
#pragma unroll
            for (int r = 0; r < R_RD; r++) {
                const int base = r * 32;
                const int u = base + lane;
                // tanh freeze: only statically-possible slices; one uniform
                // guard limits MUFU work to the ~2 truly active slices/step.
                if (r >= FR_LO && r <= FR_HI) {
                    if (base < L && base + 32 > fLo) {       // warp-uniform
                        const bool fr = (u >= fLo) & (u < L);
#pragma unroll
                        for (int j = 0; j < 4; j++) {
                            float t = tanh_fast(s[j][r]);
                            s[j][r] = fr ? t : s[j][r];
                        }
                    }
                }
                // branch-free accumulate: unconditional LDS (in-bounds by
                // construction), predicated FMA via select.
                const float2 w = w2s[u];
                const bool p = (u < L);
#pragma unroll
                for (int j = 0; j < 4; j++) {
                    as[j] = p ? fmaf(s[j][r], w.x, as[j]) : as[j];
                    al[j] = p ? fmaf(s[j][r], w.y, al[j]) : al[j];
                }
            }
            // butterfly reduce across the warp (result on all lanes)
#pragma unroll
            for (int off = 16; off; off >>= 1) {
#pragma unroll
                for (int j = 0; j < 4; j++) {
                    as[j] += __shfl_xor_sync(0xffffffffu, as[j], off);
                    al[j] += __shfl_xor_sync(0xffffffffu, al[j], off);
                }
            }

            const float sb = __shfl_sync(0xffffffffu, b2s, d);
            const float lb = __shfl_sync(0xffffffffu, b2l, d);
            float yv[4];
#pragma unroll
            for (int j = 0; j < 4; j++) {
                float sh = as[j] + sb;
                float ls = al[j] + lb;
                float xd = __shfl_sync(0xffffffffu, xv[j], d);
                yv[j] = fmaf(xd, __expf(ls), sh);
                ld[j] += ls;
                yacc[j] = (lane == d) ? yv[j] : yacc[j];
            }

            // rank-1 update of the not-yet-frozen suffix (deg >= d+1),
            // branch-free: unconditional LDS + predicated FMA.
#pragma unroll
            for (int r = R_UP; r < 32; r++) {
                const int u = r * 32 + lane;
                const float w = w1s[u];
                const bool p = (u >= L);
#pragma unroll
                for (int j = 0; j < 4; j++)
                    s[j][r] = p ? fmaf(yv[j], w, s[j][r]) : s[j][r];
            }
            o2 += L; o1 += HH - L;
        }
    }

    // outputs: y [N,D] then log_det [N]
#pragma unroll
    for (int j = 0; j < 4; j++) {
        out[(size_t)(nb + j) * DD + lane] = yacc[j];
        if (lane == 0) out[(size_t)NN * DD + (nb + j)] = ld[j];
    }
}

// ---------------------------------------------------------------------------
extern "C" void kernel_launch(void* const* d_in, const int* in_sizes, int n_in,
                              void* d_out, int out_size) {
    const float* x   = (const float*)d_in[0];
    const float* ctx = (const float*)d_in[1];
    const float* W1  = (const float*)d_in[2];
    const float* b1  = (const float*)d_in[3];
    const float* Wc  = (const float*)d_in[4];
    const float* W2  = (const float*)d_in[5];
    const float* b2  = (const float*)d_in[6];
    float* out = (float*)d_out;

    // Host-side attribute set (not an allocation; idempotent, capture-safe).
    static int smem_set = 0;
    if (!smem_set) {
        cudaFuncSetAttribute(k_main, cudaFuncAttributeMaxDynamicSharedMemorySize,
                             SMEM_MAIN_BYTES);
        smem_set = 1;
    }

    k_permute<<<(HH + 127) / 128, 128>>>(W1, b1, Wc, W2);
    k_pregemm<<<(NN / 16) * (HH / 64) / 4, 128>>>(ctx);   // 16384 blocks x 4 warps
    k_main<<<NN / 32, 256, SMEM_MAIN_BYTES>>>(x, b2, out);
}

// round 14
// speedup vs baseline: 1.2434x; 1.2434x over previous
#include <cuda_runtime.h>
#include <cuda_bf16.h>
#include <mma.h>

// Problem sizes (fixed by the dataset)
#define NN 65536
#define DD 32
#define HH 1024
#define CC 64

#define NTILES   (NN / 32)     // 2048 row-tiles of 32 rows
#define PGRID    148           // persistent grid: one CTA per SM

// Triangular staged-weight layout (see k_main):
//   sw2 region: sum_d L(d)      = 16399 float2  (L(d)=33d+1, L(0)=0)
//   sw1 region: sum_d (1024-L)  = 16369 float
#define SW2_F2   16399
#define SW1_F    16369
#define SW2_BYTES (SW2_F2 * 8)
#define SMEM_MAIN_BYTES (SW2_BYTES + SW1_F * 4)   // 196,668 B < 228 KB

// Degree-sorted unit layout:
//   deg(h) = h % 31 + 1; sorted prefix cum(g) = 33g+1 holds exactly units deg<=g
//   (deg 1 has 34 units, deg 2..31 have 33 each; cum(31)=1024).
// perm(j) = original unit index of sorted slot j.
__device__ __forceinline__ int perm_unit(int j) {
    int g, k;
    if (j < 34) { g = 1; k = j; }
    else        { g = (j - 1) / 33 + 1; k = j - (33 * (g - 1) + 1); }
    return (g - 1) + 31 * k;
}

// Fast, accurate-enough tanh: 1 - 2/(1+e^{2x}); abs err ~1e-6, saturates.
__device__ __forceinline__ float tanh_fast(float v) {
    float e, r;
    asm("ex2.approx.f32 %0, %1;" : "=f"(e) : "f"(v * 2.885390081777927f)); // 2*log2(e)
    asm("rcp.approx.f32 %0, %1;" : "=f"(r) : "f"(e + 1.0f));
    return fmaf(-2.0f, r, 1.0f);
}

// Scratch (device globals: allocation-free per harness rules)
__device__ float  g_pre[(size_t)NN * HH];   // 256 MB: context@Wc + b1 (permuted cols)
__device__ float  g_W1p[DD * HH];           // W1p[d][j] = W1[d][perm(j)]
__device__ float2 g_W2p[DD * HH];           // W2p[d][j] = W2[perm(j)][d][0..1]
__device__ float  g_Wcp[CC * HH];           // Wcp[c][j] = Wc[c][perm(j)]
__device__ float  g_b1p[HH];

// ---------------------------------------------------------------------------
// Kernel 1: permute weights into degree-sorted order
// ---------------------------------------------------------------------------
__global__ void k_permute(const float* __restrict__ W1, const float* __restrict__ b1,
                          const float* __restrict__ Wc, const float* __restrict__ W2) {
    int j = blockIdx.x * blockDim.x + threadIdx.x;
    if (j >= HH) return;
    int h = perm_unit(j);
    g_b1p[j] = b1[h];
#pragma unroll
    for (int d = 0; d < DD; d++) g_W1p[d * HH + j] = W1[d * HH + h];
#pragma unroll
    for (int c = 0; c < CC; c++) g_Wcp[c * HH + j] = Wc[c * HH + h];
#pragma unroll
    for (int d = 0; d < DD; d++)
        g_W2p[d * HH + j] = make_float2(W2[h * (DD * 2) + d * 2 + 0],
                                        W2[h * (DD * 2) + d * 2 + 1]);
}

// ---------------------------------------------------------------------------
// Kernel 2: pre[n][j] = sum_c context[n][c] * Wcp[c][j] + b1p[j]
// tf32x3 wmma (m16n16k8), fp32 accumulate. Block shares one 64-col B tile.
// ---------------------------------------------------------------------------
__global__ __launch_bounds__(128)
void k_pregemm(const float* __restrict__ ctx) {
    using namespace nvcuda;
    __shared__ float tile[4][16 * 64];

    int warpId = threadIdx.x >> 5;
    int lane   = threadIdx.x & 31;
    int ct = blockIdx.x & 15;                     // col group: 64 cols (shared by block)
    int rt = (blockIdx.x >> 4) * 4 + warpId;      // row tile: 16 rows (per warp)

    const float* Aptr = ctx + (size_t)rt * 16 * CC;

    wmma::fragment<wmma::accumulator, 16, 16, 8, float> acc[4];
#pragma unroll
    for (int c = 0; c < 4; c++) wmma::fill_fragment(acc[c], 0.0f);

#pragma unroll
    for (int k = 0; k < CC; k += 8) {
        wmma::fragment<wmma::matrix_a, 16, 16, 8, wmma::precision::tf32, wmma::row_major> aHi, aLo;
        wmma::load_matrix_sync(aHi, Aptr + k, CC);
#pragma unroll
        for (int t = 0; t < aHi.num_elements; t++) {
            float f  = aHi.x[t];
            float hi = wmma::__float_to_tf32(f);
            aHi.x[t] = hi;
            aLo.x[t] = wmma::__float_to_tf32(f - hi);
        }
#pragma unroll
        for (int c = 0; c < 4; c++) {
            wmma::fragment<wmma::matrix_b, 16, 16, 8, wmma::precision::tf32, wmma::row_major> bHi, bLo;
            wmma::load_matrix_sync(bHi, g_Wcp + k * HH + ct * 64 + c * 16, HH);
#pragma unroll
            for (int t = 0; t < bHi.num_elements; t++) {
                float f  = bHi.x[t];
                float hi = wmma::__float_to_tf32(f);
                bHi.x[t] = hi;
                bLo.x[t] = wmma::__float_to_tf32(f - hi);
            }
            wmma::mma_sync(acc[c], aHi, bHi, acc[c]);
            wmma::mma_sync(acc[c], aLo, bHi, acc[c]);
            wmma::mma_sync(acc[c], aHi, bLo, acc[c]);
        }
    }

    float* tw = &tile[warpId][0];
#pragma unroll
    for (int c = 0; c < 4; c++)
        wmma::store_matrix_sync(tw + c * 16, acc[c], 64, wmma::mem_row_major);
    __syncwarp();

    for (int i = lane; i < 16 * 64; i += 32) {
        int r = i >> 6, cc = i & 63;
        int col = ct * 64 + cc;
        g_pre[(size_t)(rt * 16 + r) * HH + col] = tw[r * 64 + cc] + g_b1p[col];
    }
}

// ---------------------------------------------------------------------------
// Capture-index shim: trivial kernel so the ncu capture (launch index 5)
// lands on k_main instead of k_permute. Deterministic no-op.
// ---------------------------------------------------------------------------
__global__ void k_shim() {}

// ---------------------------------------------------------------------------
// Kernel 3: PERSISTENT sequential MADE sampling. Grid = 148 (1 CTA/SM forced
// by 196KB smem); each block walks ~14 row-tiles, staging the triangular
// weight set ONCE. Inner loops use the measured-best R11 branch-guarded form;
// tanh restricted to the statically-possible band per group. One warp owns 4
// rows; state in registers; 4 unrolled groups x 8 rolled d-steps.
// ---------------------------------------------------------------------------
__global__ __launch_bounds__(256, 1)
void k_main(const float* __restrict__ x, const float* __restrict__ b2,
            float* __restrict__ out) {
    extern __shared__ char dynsmem[];
    float2* sm2 = (float2*)dynsmem;               // packed W2 prefixes
    float*  sm1 = (float*)(dynsmem + SW2_BYTES);  // packed W1 suffixes

    const int tid = threadIdx.x;
    const int lane = tid & 31;
    const int warpId = tid >> 5;

    // -------- stage the full triangular weight set (ONCE per SM) --------
    {
        int o1 = 0, o2 = 0;
        for (int d = 0; d < DD; d++) {
            const int L = d ? 33 * d + 1 : 0;
            for (int i = tid; i < L; i += 256)      sm2[o2 + i] = g_W2p[d * HH + i];
            for (int i = tid; i < HH - L; i += 256) sm1[o1 + i] = g_W1p[d * HH + L + i];
            o2 += L; o1 += HH - L;
        }
    }
    // b2 held lane-wise: lane d owns (shift_bias, logscale_bias) of dim d
    const float b2s = b2[2 * lane + 0];
    const float b2l = b2[2 * lane + 1];

    __syncthreads();   // staged weights visible; only barrier in the kernel

    // -------- persistent tile loop --------
    for (int t = blockIdx.x; t < NTILES; t += PGRID) {
        const int nb = t * 32 + warpId * 4;   // 4 consecutive rows per warp

        float s[4][32];
        float xv[4], yacc[4], ld[4];
#pragma unroll
        for (int j = 0; j < 4; j++) {
            const float* p = g_pre + (size_t)(nb + j) * HH;
#pragma unroll
            for (int r = 0; r < 32; r++) s[j][r] = p[r * 32 + lane];
            xv[j] = x[(nb + j) * DD + lane];
            yacc[j] = 0.f; ld[j] = 0.f;
        }

        int o1 = 0, o2 = 0;
#pragma unroll
        for (int grp = 0; grp < 4; grp++) {
            const int R_RD  = 8 * (grp + 1);              // read slices [0, R_RD)
            const int R_UP  = 8 * grp;                    // update slices [R_UP, 32)
            const int FR_LO = (grp > 0) ? 8 * grp - 1 : 0; // static tanh band
            const int FR_HI = 8 * grp + 7;

#pragma unroll 1
            for (int dd = 0; dd < 8; dd++) {
                const int d   = grp * 8 + dd;
                const int L   = d ? 33 * d + 1 : 0;              // read set [0, L)
                const int fLo = (d >= 2) ? 33 * (d - 1) + 1 : 0; // freeze [fLo, L)
                const float2* w2s = sm2 + o2;                    // valid u in [0, L)
                const float*  w1s = sm1 + (o1 - L);              // valid u in [L, 1024)

                float as[4] = {0.f, 0.f, 0.f, 0.f};
                float al[4] = {0.f, 0.f, 0.f, 0.f};
#pragma unroll
                for (int r = 0; r < R_RD; r++) {
                    const int base = r * 32;
                    const int u = base + lane;
                    if (r >= FR_LO && r <= FR_HI) {           // static tanh band
                        if (base < L && base + 32 > fLo) {    // warp-uniform
                            if (u >= fLo && u < L) {
#pragma unroll
                                for (int j = 0; j < 4; j++) s[j][r] = tanh_fast(s[j][r]);
                            }
                        }
                    }
                    if (base < L) {                           // warp-uniform
                        float2 w = w2s[u];
                        if (u < L) {
#pragma unroll
                            for (int j = 0; j < 4; j++) {
                                as[j] = fmaf(s[j][r], w.x, as[j]);
                                al[j] = fmaf(s[j][r], w.y, al[j]);
                            }
                        }
                    }
                }
                // butterfly reduce across the warp (result on all lanes)
#pragma unroll
                for (int off = 16; off; off >>= 1) {
#pragma unroll
                    for (int j = 0; j < 4; j++) {
                        as[j] += __shfl_xor_sync(0xffffffffu, as[j], off);
                        al[j] += __shfl_xor_sync(0xffffffffu, al[j], off);
                    }
                }

                const float sb = __shfl_sync(0xffffffffu, b2s, d);
                const float lb = __shfl_sync(0xffffffffu, b2l, d);
                float yv[4];
#pragma unroll
                for (int j = 0; j < 4; j++) {
                    float sh = as[j] + sb;
                    float ls = al[j] + lb;
                    float xd = __shfl_sync(0xffffffffu, xv[j], d);
                    yv[j] = fmaf(xd, __expf(ls), sh);
                    ld[j] += ls;
                    if (lane == d) yacc[j] = yv[j];
                }

                // rank-1 update of the not-yet-frozen suffix (deg >= d+1)
#pragma unroll
                for (int r = R_UP; r < 32; r++) {
                    const int base = r * 32;
                    const int u = base + lane;
                    if (base + 32 > L) {                      // warp-uniform
                        float w = w1s[u];
                        if (u >= L) {
#pragma unroll
                            for (int j = 0; j < 4; j++) s[j][r] = fmaf(yv[j], w, s[j][r]);
                        }
                    }
                }
                o2 += L; o1 += HH - L;
            }
        }

        // outputs: y [N,D] then log_det [N]
#pragma unroll
        for (int j = 0; j < 4; j++) {
            out[(size_t)(nb + j) * DD + lane] = yacc[j];
            if (lane == 0) out[(size_t)NN * DD + (nb + j)] = ld[j];
        }
    }
}

// ---------------------------------------------------------------------------
extern "C" void kernel_launch(void* const* d_in, const int* in_sizes, int n_in,
                              void* d_out, int out_size) {
    const float* x   = (const float*)d_in[0];
    const float* ctx = (const float*)d_in[1];
    const float* W1  = (const float*)d_in[2];
    const float* b1  = (const float*)d_in[3];
    const float* Wc  = (const float*)d_in[4];
    const float* W2  = (const float*)d_in[5];
    const float* b2  = (const float*)d_in[6];
    float* out = (float*)d_out;

    // Host-side attribute set (not an allocation; idempotent, capture-safe).
    static int smem_set = 0;
    if (!smem_set) {
        cudaFuncSetAttribute(k_main, cudaFuncAttributeMaxDynamicSharedMemorySize,
                             SMEM_MAIN_BYTES);
        smem_set = 1;
    }

    k_permute<<<(HH + 127) / 128, 128>>>(W1, b1, Wc, W2);
    k_pregemm<<<(NN / 16) * (HH / 64) / 4, 128>>>(ctx);   // 4096 blocks x 4 warps
    k_shim<<<1, 32>>>();                                  // shifts ncu capture onto k_main
    k_main<<<PGRID, 256, SMEM_MAIN_BYTES>>>(x, b2, out);
}